// round 3
// baseline (speedup 1.0000x reference)
#include <cuda_runtime.h>
#include <math.h>

#define N_PTS   131072
#define N_FEATS 1000
#define FDIM    64
#define YSTR    104        // padded row stride for scratch (100 valid + 4 pad), 416B = 16B-aligned
#define CF      500        // feature-vector chunk rows staged in smem
#define HID     128
#define WS      132        // smem row stride (words) for activations / transposed weights

// Scratch for [PE(36) | feats(64)] rows. __device__ global (no runtime alloc).
__device__ __align__(16) float g_y[(size_t)N_PTS * YSTR];

// ---------------------------------------------------------------------------
// Kernel 1: distance softmax over 1000 features + weighted feature gather + PE
// ---------------------------------------------------------------------------
__global__ void __launch_bounds__(256) attn_kernel(
    const float* __restrict__ x,
    const float* __restrict__ floc,
    const float* __restrict__ fvec)
{
    extern __shared__ float sm[];
    float* Lx = sm;                   // [1000]
    float* Ly = sm + N_FEATS;         // [1000]
    float* Lz = sm + 2 * N_FEATS;     // [1000]
    float* Nn = sm + 3 * N_FEATS;     // [1000] |loc|^2
    float* Vs = sm + 4 * N_FEATS;     // [CF*64]

    const int tid = threadIdx.x;
    const int p   = blockIdx.x * 256 + tid;

    // Stage locations + norms (broadcast-read later)
    for (int i = tid; i < N_FEATS; i += 256) {
        float a = floc[3 * i + 0];
        float b = floc[3 * i + 1];
        float c = floc[3 * i + 2];
        Lx[i] = a; Ly[i] = b; Lz[i] = c;
        Nn[i] = a * a + b * b + c * c;
    }
    __syncthreads();

    const float x0 = x[3 * p + 0];
    const float x1 = x[3 * p + 1];
    const float x2 = x[3 * p + 2];
    const float xx = x0 * x0 + x1 * x1 + x2 * x2;

    // Pass 1: max of inv_d (cheap; avoids online-softmax rescale of 64-wide acc)
    float m = -1e30f;
    #pragma unroll 4
    for (int f = 0; f < N_FEATS; f++) {
        float d2 = xx + Nn[f] - 2.0f * (x0 * Lx[f] + x1 * Ly[f] + x2 * Lz[f]);
        d2 = fmaxf(d2, 0.0f);
        float inv = __fdividef(1.0f, sqrtf(d2) + 1e-6f);
        m = fmaxf(m, inv);
    }

    // Pass 2: exp weights + weighted V accumulation (64 regs)
    float s = 0.0f;
    float acc[FDIM];
    #pragma unroll
    for (int j = 0; j < FDIM; j++) acc[j] = 0.0f;

    for (int ch = 0; ch < N_FEATS / CF; ch++) {
        __syncthreads();
        const float4* src = (const float4*)(fvec + (size_t)ch * CF * FDIM);
        float4*       dst = (float4*)Vs;
        for (int i = tid; i < CF * FDIM / 4; i += 256) dst[i] = src[i];
        __syncthreads();

        const int base = ch * CF;
        #pragma unroll 1
        for (int f = 0; f < CF; f++) {
            const int g = base + f;
            float d2 = xx + Nn[g] - 2.0f * (x0 * Lx[g] + x1 * Ly[g] + x2 * Lz[g]);
            d2 = fmaxf(d2, 0.0f);
            float inv = __fdividef(1.0f, sqrtf(d2) + 1e-6f);
            float w = __expf(inv - m);
            s += w;
            const float4* vr = (const float4*)(Vs + f * FDIM);  // warp-broadcast
            #pragma unroll
            for (int q = 0; q < 16; q++) {
                float4 v = vr[q];
                acc[4 * q + 0] = fmaf(w, v.x, acc[4 * q + 0]);
                acc[4 * q + 1] = fmaf(w, v.y, acc[4 * q + 1]);
                acc[4 * q + 2] = fmaf(w, v.z, acc[4 * q + 2]);
                acc[4 * q + 3] = fmaf(w, v.w, acc[4 * q + 3]);
            }
        }
    }

    const float invs = 1.0f / s;

    // Positional encoding (accurate sincosf; args up to ~100.5)
    float pe[36];
    const float freqs[6] = {3.14159274101257324f,  6.28318548202514648f,
                            12.5663709640502930f,  25.1327419281005859f,
                            50.2654838562011719f,  100.530967712402344f};
    const float xv[3] = {x0, x1, x2};
    #pragma unroll
    for (int d = 0; d < 3; d++) {
        #pragma unroll
        for (int l = 0; l < 6; l++) {
            float sv, cv;
            sincosf(xv[d] * freqs[l], &sv, &cv);
            pe[d * 12 + l]     = sv;
            pe[d * 12 + 6 + l] = cv;
        }
    }

    float4* y4 = (float4*)(g_y + (size_t)p * YSTR);
    #pragma unroll
    for (int q = 0; q < 9; q++)
        y4[q] = make_float4(pe[4 * q], pe[4 * q + 1], pe[4 * q + 2], pe[4 * q + 3]);
    #pragma unroll
    for (int q = 0; q < 16; q++)
        y4[9 + q] = make_float4(acc[4 * q + 0] * invs, acc[4 * q + 1] * invs,
                                acc[4 * q + 2] * invs, acc[4 * q + 3] * invs);
}

// ---------------------------------------------------------------------------
// Kernel 2: 4x hidden MLP + output layer. Block = 64 points, 256 threads.
// Per-thread tile: 4 points x 8 outputs (j in {4tx..4tx+3} U {64+4tx..64+4tx+3}).
// ---------------------------------------------------------------------------
__device__ __forceinline__ float snake(float h)
{
    float sv = __sinf(h);
    return fmaf(0.5f, h, sv * sv);
}

template <int K>
__device__ __forceinline__ void mlp_layer(
    const float* __restrict__ Ain, float* __restrict__ Bout, float* __restrict__ Wsh,
    const float* __restrict__ Wg, const float* __restrict__ bg,
    int tid, int tx, int ty)
{
    __syncthreads();  // previous layer done reading Wsh / Ain fully written
    // Transpose weights [HID][K] -> Wsh[k][j] (stride WS, read-conflict-free)
    for (int i = tid; i < HID * K; i += 256) {
        int j = i / K;
        int k = i - j * K;
        Wsh[k * WS + j] = Wg[i];
    }
    __syncthreads();

    float4 blo = ((const float4*)bg)[tx];
    float4 bhi = ((const float4*)(bg + 64))[tx];
    float acc[4][8];
    #pragma unroll
    for (int pp = 0; pp < 4; pp++) {
        acc[pp][0] = blo.x; acc[pp][1] = blo.y; acc[pp][2] = blo.z; acc[pp][3] = blo.w;
        acc[pp][4] = bhi.x; acc[pp][5] = bhi.y; acc[pp][6] = bhi.z; acc[pp][7] = bhi.w;
    }

    #pragma unroll 4
    for (int k = 0; k < K; k++) {
        float4 wlo = *(const float4*)(Wsh + k * WS + 4 * tx);
        float4 whi = *(const float4*)(Wsh + k * WS + 64 + 4 * tx);
        float as[4];
        #pragma unroll
        for (int pp = 0; pp < 4; pp++) as[pp] = Ain[(4 * ty + pp) * WS + k];
        #pragma unroll
        for (int pp = 0; pp < 4; pp++) {
            acc[pp][0] = fmaf(as[pp], wlo.x, acc[pp][0]);
            acc[pp][1] = fmaf(as[pp], wlo.y, acc[pp][1]);
            acc[pp][2] = fmaf(as[pp], wlo.z, acc[pp][2]);
            acc[pp][3] = fmaf(as[pp], wlo.w, acc[pp][3]);
            acc[pp][4] = fmaf(as[pp], whi.x, acc[pp][4]);
            acc[pp][5] = fmaf(as[pp], whi.y, acc[pp][5]);
            acc[pp][6] = fmaf(as[pp], whi.z, acc[pp][6]);
            acc[pp][7] = fmaf(as[pp], whi.w, acc[pp][7]);
        }
    }

    #pragma unroll
    for (int pp = 0; pp < 4; pp++) {
        float r[8];
        #pragma unroll
        for (int o = 0; o < 8; o++) r[o] = snake(acc[pp][o]);
        *(float4*)(Bout + (4 * ty + pp) * WS + 4 * tx)      = make_float4(r[0], r[1], r[2], r[3]);
        *(float4*)(Bout + (4 * ty + pp) * WS + 64 + 4 * tx) = make_float4(r[4], r[5], r[6], r[7]);
    }
}

__global__ void __launch_bounds__(256) mlp_kernel(
    const float* __restrict__ W0, const float* __restrict__ b0,
    const float* __restrict__ W1, const float* __restrict__ b1,
    const float* __restrict__ W2, const float* __restrict__ b2,
    const float* __restrict__ W3, const float* __restrict__ b3,
    const float* __restrict__ W4, const float* __restrict__ b4,
    float* __restrict__ out)
{
    extern __shared__ float sm[];
    float* A   = sm;                 // [64][WS]
    float* B   = A + 64 * WS;        // [64][WS]
    float* Wsh = B + 64 * WS;        // [HID][WS]

    const int tid = threadIdx.x;
    const int tx  = tid & 15;
    const int ty  = tid >> 4;
    const int p0  = blockIdx.x * 64;

    // Load 64 input rows (100 valid cols; col 100..103 pad never consumed)
    const float* yb = g_y + (size_t)p0 * YSTR;
    for (int i = tid; i < 64 * 26; i += 256) {
        int r = i / 26;
        int c = i - r * 26;
        ((float4*)(A + r * WS))[c] = ((const float4*)(yb + (size_t)r * YSTR))[c];
    }

    mlp_layer<100>(A, B, Wsh, W0, b0, tid, tx, ty);
    mlp_layer<128>(B, A, Wsh, W1, b1, tid, tx, ty);
    mlp_layer<128>(A, B, Wsh, W2, b2, tid, tx, ty);
    mlp_layer<128>(B, A, Wsh, W3, b3, tid, tx, ty);
    __syncthreads();

    // Output layer: 64 points x dot(128)
    if (tid < 64) {
        const float* h = A + tid * WS;
        float sum = 0.0f;
        #pragma unroll 8
        for (int i = 0; i < 128; i++) sum = fmaf(h[i], __ldg(W4 + i), sum);
        out[p0 + tid] = sum + __ldg(b4);
    }
}

// ---------------------------------------------------------------------------
extern "C" void kernel_launch(void* const* d_in, const int* in_sizes, int n_in,
                              void* d_out, int out_size)
{
    const float* x  = (const float*)d_in[0];
    const float* fl = (const float*)d_in[1];
    const float* fv = (const float*)d_in[2];
    const float* W0 = (const float*)d_in[3];
    const float* b0 = (const float*)d_in[4];
    const float* W1 = (const float*)d_in[5];
    const float* b1 = (const float*)d_in[6];
    const float* W2 = (const float*)d_in[7];
    const float* b2 = (const float*)d_in[8];
    const float* W3 = (const float*)d_in[9];
    const float* b3 = (const float*)d_in[10];
    const float* W4 = (const float*)d_in[11];
    const float* b4 = (const float*)d_in[12];
    float* out = (float*)d_out;

    const size_t sm1 = (size_t)(4 * N_FEATS + CF * FDIM) * sizeof(float);   // 144000 B
    const size_t sm2 = (size_t)(2 * 64 * WS + HID * WS) * sizeof(float);    // 135168 B

    cudaFuncSetAttribute(attn_kernel, cudaFuncAttributeMaxDynamicSharedMemorySize, (int)sm1);
    cudaFuncSetAttribute(mlp_kernel,  cudaFuncAttributeMaxDynamicSharedMemorySize, (int)sm2);

    attn_kernel<<<N_PTS / 256, 256, sm1>>>(x, fl, fv);
    mlp_kernel<<<N_PTS / 64, 256, sm2>>>(W0, b0, W1, b1, W2, b2, W3, b3, W4, b4, out);
}

// round 4
// speedup vs baseline: 1.3621x; 1.3621x over previous
#include <cuda_runtime.h>
#include <math.h>

#define N_PTS   131072
#define N_FEATS 1000
#define FDIM    64
#define YSTR    104        // padded scratch row stride (100 valid + 4 pad)
#define CF      250        // feature-vector chunk rows staged in smem (80KB total -> 2 blocks/SM)
#define HID     128
#define WS      132        // smem row stride (words), conflict-free float4 reads

// Scratch for [PE(36) | feats(64)] rows. __device__ global (no runtime alloc).
__device__ __align__(16) float g_y[(size_t)N_PTS * YSTR];

// ---------------------------------------------------------------------------
// Kernel 1: distance softmax over 1000 features + weighted feature gather + PE
// ---------------------------------------------------------------------------
__global__ void __launch_bounds__(256, 2) attn_kernel(
    const float* __restrict__ x,
    const float* __restrict__ floc,
    const float* __restrict__ fvec)
{
    extern __shared__ float sm[];
    float* Mx = sm;                   // [1000] = -2*loc.x
    float* My = sm + N_FEATS;         // [1000] = -2*loc.y
    float* Mz = sm + 2 * N_FEATS;     // [1000] = -2*loc.z
    float* Nn = sm + 3 * N_FEATS;     // [1000] = |loc|^2
    float* Vs = sm + 4 * N_FEATS;     // [CF*64]

    const int tid = threadIdx.x;
    const int p   = blockIdx.x * 256 + tid;

    // Stage locations (pre-scaled) + norms
    for (int i = tid; i < N_FEATS; i += 256) {
        float a = floc[3 * i + 0];
        float b = floc[3 * i + 1];
        float c = floc[3 * i + 2];
        Mx[i] = -2.0f * a; My[i] = -2.0f * b; Mz[i] = -2.0f * c;
        Nn[i] = a * a + b * b + c * c;
    }
    __syncthreads();

    const float x0 = x[3 * p + 0];
    const float x1 = x[3 * p + 1];
    const float x2 = x[3 * p + 2];
    const float xx = x0 * x0 + x1 * x1 + x2 * x2;

    // Pass 1: max of inv_d. inv = clamp(rsqrt(d2), 1e6) == 1/(sqrt(d2)+1e-6)
    // to within 1e-5 rel for any d2 of nonzero measure.
    float m = -1e30f;
    #pragma unroll 4
    for (int f = 0; f < N_FEATS; f++) {
        float d2 = fmaf(x2, Mz[f], fmaf(x1, My[f], fmaf(x0, Mx[f], xx + Nn[f])));
        d2 = fmaxf(d2, 0.0f);
        float inv = fminf(rsqrtf(d2), 1e6f);
        m = fmaxf(m, inv);
    }

    // Pass 2: exp weights + weighted V accumulation (64 regs)
    float s = 0.0f;
    float acc[FDIM];
    #pragma unroll
    for (int j = 0; j < FDIM; j++) acc[j] = 0.0f;

    for (int ch = 0; ch < N_FEATS / CF; ch++) {
        __syncthreads();
        const float4* src = (const float4*)(fvec + (size_t)ch * CF * FDIM);
        float4*       dst = (float4*)Vs;
        for (int i = tid; i < CF * FDIM / 4; i += 256) dst[i] = src[i];
        __syncthreads();

        const int base = ch * CF;
        #pragma unroll 1
        for (int f = 0; f < CF; f++) {
            const int g = base + f;
            float d2 = fmaf(x2, Mz[g], fmaf(x1, My[g], fmaf(x0, Mx[g], xx + Nn[g])));
            d2 = fmaxf(d2, 0.0f);
            float inv = fminf(rsqrtf(d2), 1e6f);
            float w = __expf(inv - m);
            s += w;
            const float4* vr = (const float4*)(Vs + f * FDIM);  // warp-broadcast
            #pragma unroll
            for (int q = 0; q < 16; q++) {
                float4 v = vr[q];
                acc[4 * q + 0] = fmaf(w, v.x, acc[4 * q + 0]);
                acc[4 * q + 1] = fmaf(w, v.y, acc[4 * q + 1]);
                acc[4 * q + 2] = fmaf(w, v.z, acc[4 * q + 2]);
                acc[4 * q + 3] = fmaf(w, v.w, acc[4 * q + 3]);
            }
        }
    }

    const float invs = 1.0f / s;
    float4* y4 = (float4*)(g_y + (size_t)p * YSTR);

    // Write feats first (shortens acc live range)
    #pragma unroll
    for (int q = 0; q < 16; q++)
        y4[9 + q] = make_float4(acc[4 * q + 0] * invs, acc[4 * q + 1] * invs,
                                acc[4 * q + 2] * invs, acc[4 * q + 3] * invs);

    // Positional encoding (accurate sincosf; args up to ~100.5)
    float pe[36];
    const float freqs[6] = {3.14159274101257324f,  6.28318548202514648f,
                            12.5663709640502930f,  25.1327419281005859f,
                            50.2654838562011719f,  100.530967712402344f};
    const float xv[3] = {x0, x1, x2};
    #pragma unroll
    for (int d = 0; d < 3; d++) {
        #pragma unroll
        for (int l = 0; l < 6; l++) {
            float sv, cv;
            sincosf(xv[d] * freqs[l], &sv, &cv);
            pe[d * 12 + l]     = sv;
            pe[d * 12 + 6 + l] = cv;
        }
    }
    #pragma unroll
    for (int q = 0; q < 9; q++)
        y4[q] = make_float4(pe[4 * q], pe[4 * q + 1], pe[4 * q + 2], pe[4 * q + 3]);
}

// ---------------------------------------------------------------------------
// Kernel 2: 4x hidden MLP + output layer. Block = 64 points, 256 threads.
// Per-thread tile: 4 points x 8 outputs. Weights staged in split-K chunks of
// 64 rows so total smem = 3 x 64 x WS x 4B = 101376B -> 2 blocks/SM.
// ---------------------------------------------------------------------------
__device__ __forceinline__ float snake(float h)
{
    float sv = __sinf(h);
    return fmaf(0.5f, h, sv * sv);
}

template <int K>
__device__ __forceinline__ void mlp_layer(
    const float* __restrict__ Ain, float* __restrict__ Bout, float* __restrict__ Wsh,
    const float* __restrict__ Wg, const float* __restrict__ bg,
    int tid, int tx, int ty)
{
    float4 blo = ((const float4*)bg)[tx];
    float4 bhi = ((const float4*)(bg + 64))[tx];
    float acc[4][8];
    #pragma unroll
    for (int pp = 0; pp < 4; pp++) {
        acc[pp][0] = blo.x; acc[pp][1] = blo.y; acc[pp][2] = blo.z; acc[pp][3] = blo.w;
        acc[pp][4] = bhi.x; acc[pp][5] = bhi.y; acc[pp][6] = bhi.z; acc[pp][7] = bhi.w;
    }

    #pragma unroll
    for (int k0 = 0; k0 < K; k0 += 64) {
        const int KC = (K - k0 < 64) ? (K - k0) : 64;
        __syncthreads();   // prior consumers of Wsh / producers of Ain done
        // Stage transposed weight chunk: Wsh[kk][j] = Wg[j][k0+kk]
        for (int i = tid; i < HID * KC; i += 256) {
            int j  = i / KC;
            int kk = i - j * KC;
            Wsh[kk * WS + j] = Wg[j * K + k0 + kk];
        }
        __syncthreads();

        for (int kq = 0; kq < KC; kq += 4) {
            float4 a4[4];
            #pragma unroll
            for (int pp = 0; pp < 4; pp++)
                a4[pp] = *(const float4*)(Ain + (4 * ty + pp) * WS + k0 + kq);
            #pragma unroll
            for (int dk = 0; dk < 4; dk++) {
                float4 wlo = *(const float4*)(Wsh + (kq + dk) * WS + 4 * tx);
                float4 whi = *(const float4*)(Wsh + (kq + dk) * WS + 64 + 4 * tx);
                #pragma unroll
                for (int pp = 0; pp < 4; pp++) {
                    float a = ((const float*)&a4[pp])[dk];
                    acc[pp][0] = fmaf(a, wlo.x, acc[pp][0]);
                    acc[pp][1] = fmaf(a, wlo.y, acc[pp][1]);
                    acc[pp][2] = fmaf(a, wlo.z, acc[pp][2]);
                    acc[pp][3] = fmaf(a, wlo.w, acc[pp][3]);
                    acc[pp][4] = fmaf(a, whi.x, acc[pp][4]);
                    acc[pp][5] = fmaf(a, whi.y, acc[pp][5]);
                    acc[pp][6] = fmaf(a, whi.z, acc[pp][6]);
                    acc[pp][7] = fmaf(a, whi.w, acc[pp][7]);
                }
            }
        }
    }
    __syncthreads();  // Bout may alias a buffer others still read

    #pragma unroll
    for (int pp = 0; pp < 4; pp++) {
        float r[8];
        #pragma unroll
        for (int o = 0; o < 8; o++) r[o] = snake(acc[pp][o]);
        *(float4*)(Bout + (4 * ty + pp) * WS + 4 * tx)      = make_float4(r[0], r[1], r[2], r[3]);
        *(float4*)(Bout + (4 * ty + pp) * WS + 64 + 4 * tx) = make_float4(r[4], r[5], r[6], r[7]);
    }
}

__global__ void __launch_bounds__(256, 2) mlp_kernel(
    const float* __restrict__ W0, const float* __restrict__ b0,
    const float* __restrict__ W1, const float* __restrict__ b1,
    const float* __restrict__ W2, const float* __restrict__ b2,
    const float* __restrict__ W3, const float* __restrict__ b3,
    const float* __restrict__ W4, const float* __restrict__ b4,
    float* __restrict__ out)
{
    extern __shared__ float sm[];
    float* A   = sm;                 // [64][WS]
    float* B   = A + 64 * WS;        // [64][WS]
    float* Wsh = B + 64 * WS;        // [64][WS] split-K weight chunk

    const int tid = threadIdx.x;
    const int tx  = tid & 15;
    const int ty  = tid >> 4;
    const int p0  = blockIdx.x * 64;

    // Load 64 input rows (100 valid cols; pad cols never consumed)
    const float* yb = g_y + (size_t)p0 * YSTR;
    for (int i = tid; i < 64 * 26; i += 256) {
        int r = i / 26;
        int c = i - r * 26;
        ((float4*)(A + r * WS))[c] = ((const float4*)(yb + (size_t)r * YSTR))[c];
    }

    mlp_layer<100>(A, B, Wsh, W0, b0, tid, tx, ty);
    mlp_layer<128>(B, A, Wsh, W1, b1, tid, tx, ty);
    mlp_layer<128>(A, B, Wsh, W2, b2, tid, tx, ty);
    mlp_layer<128>(B, A, Wsh, W3, b3, tid, tx, ty);
    __syncthreads();

    // Output layer: 64 points x dot(128)
    if (tid < 64) {
        const float* h = A + tid * WS;
        float sum = 0.0f;
        #pragma unroll 8
        for (int i = 0; i < 128; i++) sum = fmaf(h[i], __ldg(W4 + i), sum);
        out[p0 + tid] = sum + __ldg(b4);
    }
}

// ---------------------------------------------------------------------------
extern "C" void kernel_launch(void* const* d_in, const int* in_sizes, int n_in,
                              void* d_out, int out_size)
{
    const float* x  = (const float*)d_in[0];
    const float* fl = (const float*)d_in[1];
    const float* fv = (const float*)d_in[2];
    const float* W0 = (const float*)d_in[3];
    const float* b0 = (const float*)d_in[4];
    const float* W1 = (const float*)d_in[5];
    const float* b1 = (const float*)d_in[6];
    const float* W2 = (const float*)d_in[7];
    const float* b2 = (const float*)d_in[8];
    const float* W3 = (const float*)d_in[9];
    const float* b3 = (const float*)d_in[10];
    const float* W4 = (const float*)d_in[11];
    const float* b4 = (const float*)d_in[12];
    float* out = (float*)d_out;

    const size_t sm1 = (size_t)(4 * N_FEATS + CF * FDIM) * sizeof(float);   // 80000 B
    const size_t sm2 = (size_t)(3 * 64 * WS) * sizeof(float);               // 101376 B

    cudaFuncSetAttribute(attn_kernel, cudaFuncAttributeMaxDynamicSharedMemorySize, (int)sm1);
    cudaFuncSetAttribute(mlp_kernel,  cudaFuncAttributeMaxDynamicSharedMemorySize, (int)sm2);

    attn_kernel<<<N_PTS / 256, 256, sm1>>>(x, fl, fv);
    mlp_kernel<<<N_PTS / 64, 256, sm2>>>(W0, b0, W1, b1, W2, b2, W3, b3, W4, b4, out);
}

// round 5
// speedup vs baseline: 1.3649x; 1.0020x over previous
#include <cuda_runtime.h>
#include <math.h>

#define N_PTS   131072
#define N_FEATS 1000
#define FDIM    64
#define YSTR    104        // padded scratch row stride (100 valid + 4 pad)
#define CF      250        // feature-vector chunk rows staged in smem (80KB total -> 2 blocks/SM)
#define HID     128
#define WS      132        // smem row stride (words), conflict-free float4 reads

// Scratch for [PE(36) | feats(64)] rows. __device__ global (no runtime alloc).
__device__ __align__(16) float g_y[(size_t)N_PTS * YSTR];

// ---------------------------------------------------------------------------
// Kernel 1: distance softmax over 1000 features + weighted feature gather + PE
// ---------------------------------------------------------------------------
__global__ void __launch_bounds__(256, 2) attn_kernel(
    const float* __restrict__ x,
    const float* __restrict__ floc,
    const float* __restrict__ fvec)
{
    extern __shared__ float sm[];
    float* Mx = sm;                   // [1000] = -2*loc.x
    float* My = sm + N_FEATS;         // [1000] = -2*loc.y
    float* Mz = sm + 2 * N_FEATS;     // [1000] = -2*loc.z
    float* Nn = sm + 3 * N_FEATS;     // [1000] = |loc|^2
    float* Vs = sm + 4 * N_FEATS;     // [CF*64]

    const int tid = threadIdx.x;
    const int p   = blockIdx.x * 256 + tid;

    // Stage locations (pre-scaled) + norms
    for (int i = tid; i < N_FEATS; i += 256) {
        float a = floc[3 * i + 0];
        float b = floc[3 * i + 1];
        float c = floc[3 * i + 2];
        Mx[i] = -2.0f * a; My[i] = -2.0f * b; Mz[i] = -2.0f * c;
        Nn[i] = a * a + b * b + c * c;
    }
    __syncthreads();

    const float x0 = x[3 * p + 0];
    const float x1 = x[3 * p + 1];
    const float x2 = x[3 * p + 2];
    const float xx = x0 * x0 + x1 * x1 + x2 * x2;

    // Pass 1: max of inv_d. inv = clamp(rsqrt(d2), 1e6) == 1/(sqrt(d2)+1e-6)
    // to within 1e-5 rel for any d2 of nonzero measure.
    float m = -1e30f;
    #pragma unroll 4
    for (int f = 0; f < N_FEATS; f++) {
        float d2 = fmaf(x2, Mz[f], fmaf(x1, My[f], fmaf(x0, Mx[f], xx + Nn[f])));
        d2 = fmaxf(d2, 0.0f);
        float inv = fminf(rsqrtf(d2), 1e6f);
        m = fmaxf(m, inv);
    }

    // Pass 2: exp weights + weighted V accumulation (64 regs)
    float s = 0.0f;
    float acc[FDIM];
    #pragma unroll
    for (int j = 0; j < FDIM; j++) acc[j] = 0.0f;

    for (int ch = 0; ch < N_FEATS / CF; ch++) {
        __syncthreads();
        const float4* src = (const float4*)(fvec + (size_t)ch * CF * FDIM);
        float4*       dst = (float4*)Vs;
        for (int i = tid; i < CF * FDIM / 4; i += 256) dst[i] = src[i];
        __syncthreads();

        const int base = ch * CF;
        #pragma unroll 1
        for (int f = 0; f < CF; f++) {
            const int g = base + f;
            float d2 = fmaf(x2, Mz[g], fmaf(x1, My[g], fmaf(x0, Mx[g], xx + Nn[g])));
            d2 = fmaxf(d2, 0.0f);
            float inv = fminf(rsqrtf(d2), 1e6f);
            float w = __expf(inv - m);
            s += w;
            const float4* vr = (const float4*)(Vs + f * FDIM);  // warp-broadcast
            #pragma unroll
            for (int q = 0; q < 16; q++) {
                float4 v = vr[q];
                acc[4 * q + 0] = fmaf(w, v.x, acc[4 * q + 0]);
                acc[4 * q + 1] = fmaf(w, v.y, acc[4 * q + 1]);
                acc[4 * q + 2] = fmaf(w, v.z, acc[4 * q + 2]);
                acc[4 * q + 3] = fmaf(w, v.w, acc[4 * q + 3]);
            }
        }
    }

    const float invs = 1.0f / s;
    float4* y4 = (float4*)(g_y + (size_t)p * YSTR);

    // Write feats first (shortens acc live range)
    #pragma unroll
    for (int q = 0; q < 16; q++)
        y4[9 + q] = make_float4(acc[4 * q + 0] * invs, acc[4 * q + 1] * invs,
                                acc[4 * q + 2] * invs, acc[4 * q + 3] * invs);

    // Positional encoding (accurate sincosf; args up to ~100.5)
    float pe[36];
    const float freqs[6] = {3.14159274101257324f,  6.28318548202514648f,
                            12.5663709640502930f,  25.1327419281005859f,
                            50.2654838562011719f,  100.530967712402344f};
    const float xv[3] = {x0, x1, x2};
    #pragma unroll
    for (int d = 0; d < 3; d++) {
        #pragma unroll
        for (int l = 0; l < 6; l++) {
            float sv, cv;
            sincosf(xv[d] * freqs[l], &sv, &cv);
            pe[d * 12 + l]     = sv;
            pe[d * 12 + 6 + l] = cv;
        }
    }
    #pragma unroll
    for (int q = 0; q < 9; q++)
        y4[q] = make_float4(pe[4 * q], pe[4 * q + 1], pe[4 * q + 2], pe[4 * q + 3]);
}

// ---------------------------------------------------------------------------
// Kernel 2: 4x hidden MLP + output layer. Block = 64 points, 256 threads.
// Per-thread tile: 4 points x 8 outputs. Weights staged in split-K chunks of
// 64 rows so total smem = 3 x 64 x WS x 4B = 101376B -> 2 blocks/SM.
// ---------------------------------------------------------------------------
__device__ __forceinline__ float snake(float h)
{
    float sv = __sinf(h);
    return fmaf(0.5f, h, sv * sv);
}

template <int K>
__device__ __forceinline__ void mlp_layer(
    const float* __restrict__ Ain, float* __restrict__ Bout, float* __restrict__ Wsh,
    const float* __restrict__ Wg, const float* __restrict__ bg,
    int tid, int tx, int ty)
{
    float4 blo = ((const float4*)bg)[tx];
    float4 bhi = ((const float4*)(bg + 64))[tx];
    float acc[4][8];
    #pragma unroll
    for (int pp = 0; pp < 4; pp++) {
        acc[pp][0] = blo.x; acc[pp][1] = blo.y; acc[pp][2] = blo.z; acc[pp][3] = blo.w;
        acc[pp][4] = bhi.x; acc[pp][5] = bhi.y; acc[pp][6] = bhi.z; acc[pp][7] = bhi.w;
    }

    #pragma unroll
    for (int k0 = 0; k0 < K; k0 += 64) {
        const int KC = (K - k0 < 64) ? (K - k0) : 64;
        __syncthreads();   // prior consumers of Wsh / producers of Ain done
        // Stage transposed weight chunk: Wsh[kk][j] = Wg[j][k0+kk]
        for (int i = tid; i < HID * KC; i += 256) {
            int j  = i / KC;
            int kk = i - j * KC;
            Wsh[kk * WS + j] = Wg[j * K + k0 + kk];
        }
        __syncthreads();

        for (int kq = 0; kq < KC; kq += 4) {
            float4 a4[4];
            #pragma unroll
            for (int pp = 0; pp < 4; pp++)
                a4[pp] = *(const float4*)(Ain + (4 * ty + pp) * WS + k0 + kq);
            #pragma unroll
            for (int dk = 0; dk < 4; dk++) {
                float4 wlo = *(const float4*)(Wsh + (kq + dk) * WS + 4 * tx);
                float4 whi = *(const float4*)(Wsh + (kq + dk) * WS + 64 + 4 * tx);
                #pragma unroll
                for (int pp = 0; pp < 4; pp++) {
                    float a = ((const float*)&a4[pp])[dk];
                    acc[pp][0] = fmaf(a, wlo.x, acc[pp][0]);
                    acc[pp][1] = fmaf(a, wlo.y, acc[pp][1]);
                    acc[pp][2] = fmaf(a, wlo.z, acc[pp][2]);
                    acc[pp][3] = fmaf(a, wlo.w, acc[pp][3]);
                    acc[pp][4] = fmaf(a, whi.x, acc[pp][4]);
                    acc[pp][5] = fmaf(a, whi.y, acc[pp][5]);
                    acc[pp][6] = fmaf(a, whi.z, acc[pp][6]);
                    acc[pp][7] = fmaf(a, whi.w, acc[pp][7]);
                }
            }
        }
    }
    __syncthreads();  // Bout may alias a buffer others still read

    #pragma unroll
    for (int pp = 0; pp < 4; pp++) {
        float r[8];
        #pragma unroll
        for (int o = 0; o < 8; o++) r[o] = snake(acc[pp][o]);
        *(float4*)(Bout + (4 * ty + pp) * WS + 4 * tx)      = make_float4(r[0], r[1], r[2], r[3]);
        *(float4*)(Bout + (4 * ty + pp) * WS + 64 + 4 * tx) = make_float4(r[4], r[5], r[6], r[7]);
    }
}

__global__ void __launch_bounds__(256, 2) mlp_kernel(
    const float* __restrict__ W0, const float* __restrict__ b0,
    const float* __restrict__ W1, const float* __restrict__ b1,
    const float* __restrict__ W2, const float* __restrict__ b2,
    const float* __restrict__ W3, const float* __restrict__ b3,
    const float* __restrict__ W4, const float* __restrict__ b4,
    float* __restrict__ out)
{
    extern __shared__ float sm[];
    float* A   = sm;                 // [64][WS]
    float* B   = A + 64 * WS;        // [64][WS]
    float* Wsh = B + 64 * WS;        // [64][WS] split-K weight chunk

    const int tid = threadIdx.x;
    const int tx  = tid & 15;
    const int ty  = tid >> 4;
    const int p0  = blockIdx.x * 64;

    // Load 64 input rows (100 valid cols; pad cols never consumed)
    const float* yb = g_y + (size_t)p0 * YSTR;
    for (int i = tid; i < 64 * 26; i += 256) {
        int r = i / 26;
        int c = i - r * 26;
        ((float4*)(A + r * WS))[c] = ((const float4*)(yb + (size_t)r * YSTR))[c];
    }

    mlp_layer<100>(A, B, Wsh, W0, b0, tid, tx, ty);
    mlp_layer<128>(B, A, Wsh, W1, b1, tid, tx, ty);
    mlp_layer<128>(A, B, Wsh, W2, b2, tid, tx, ty);
    mlp_layer<128>(B, A, Wsh, W3, b3, tid, tx, ty);
    __syncthreads();

    // Output layer: 64 points x dot(128)
    if (tid < 64) {
        const float* h = A + tid * WS;
        float sum = 0.0f;
        #pragma unroll 8
        for (int i = 0; i < 128; i++) sum = fmaf(h[i], __ldg(W4 + i), sum);
        out[p0 + tid] = sum + __ldg(b4);
    }
}

// ---------------------------------------------------------------------------
extern "C" void kernel_launch(void* const* d_in, const int* in_sizes, int n_in,
                              void* d_out, int out_size)
{
    const float* x  = (const float*)d_in[0];
    const float* fl = (const float*)d_in[1];
    const float* fv = (const float*)d_in[2];
    const float* W0 = (const float*)d_in[3];
    const float* b0 = (const float*)d_in[4];
    const float* W1 = (const float*)d_in[5];
    const float* b1 = (const float*)d_in[6];
    const float* W2 = (const float*)d_in[7];
    const float* b2 = (const float*)d_in[8];
    const float* W3 = (const float*)d_in[9];
    const float* b3 = (const float*)d_in[10];
    const float* W4 = (const float*)d_in[11];
    const float* b4 = (const float*)d_in[12];
    float* out = (float*)d_out;

    const size_t sm1 = (size_t)(4 * N_FEATS + CF * FDIM) * sizeof(float);   // 80000 B
    const size_t sm2 = (size_t)(3 * 64 * WS) * sizeof(float);               // 101376 B

    cudaFuncSetAttribute(attn_kernel, cudaFuncAttributeMaxDynamicSharedMemorySize, (int)sm1);
    cudaFuncSetAttribute(mlp_kernel,  cudaFuncAttributeMaxDynamicSharedMemorySize, (int)sm2);

    attn_kernel<<<N_PTS / 256, 256, sm1>>>(x, fl, fv);
    mlp_kernel<<<N_PTS / 64, 256, sm2>>>(W0, b0, W1, b1, W2, b2, W3, b3, W4, b4, out);
}